// round 14
// baseline (speedup 1.0000x reference)
#include <cuda_runtime.h>
#include <cuda_fp16.h>
#include <math.h>
#include <cstdint>
#include <cstddef>

// ------------------------- problem constants -------------------------------
constexpr int Bv   = 2;
constexpr int S    = 2048;
constexpr int D    = 1024;
constexpr int H    = 16;
constexpr int HD   = 64;
constexpr int M    = Bv * S;      // 4096
constexpr int DFF  = 4 * D;       // 4096
constexpr int QS   = 3 * D;       // fused qkv row stride 3072

constexpr int NSM_SLOTS = 296;    // 148 SMs x 2 CTAs

// 0.125 * log2(e): folded into Q at projection so scores are exp2-ready.
constexpr float QSCALE = 0.18033688011f;

// ------------------------- scratch (device globals) ------------------------
__device__ uint32_t g_pm[S * (S / 32)];       // bit-packed mask

__device__ __half g_xh  [M * D];
__device__ __half g_qkvh[(size_t)M * QS];
__device__ __half g_oh  [M * D];
__device__ __half g_t0h [M * D];
__device__ __half g_x1h [M * D];
__device__ __half g_hh  [(size_t)M * DFF];
__device__ __half g_h2h [M * D];
__device__ __half g_wqkvoh[(size_t)4 * D * D];   // Wq|Wk|Wv|Wo transposed
__device__ __half g_w1h[(size_t)D * DFF];
__device__ __half g_w2h[(size_t)D * DFF];

// ------------------------- small helpers -----------------------------------
__device__ __forceinline__ float gelu_exact(float x) {
    return 0.5f * x * (1.0f + erff(x * 0.70710678118654752f));
}

__device__ __forceinline__ uint32_t smem_u32(const void* p) {
    uint32_t a;
    asm("{ .reg .u64 t; cvta.to.shared.u64 t, %1; cvt.u32.u64 %0, t; }"
        : "=r"(a) : "l"(p));
    return a;
}

__device__ __forceinline__ uint32_t swz128(uint32_t x) {
    return x ^ ((x >> 3) & 0x70);
}

__device__ __forceinline__ void cpasync16(uint32_t dst, const void* src) {
    asm volatile("cp.async.cg.shared.global [%0], [%1], 16;" :: "r"(dst), "l"(src));
}

__device__ __forceinline__ void ldsm_x4(uint32_t& r0, uint32_t& r1,
                                        uint32_t& r2, uint32_t& r3, uint32_t a) {
    asm volatile("ldmatrix.sync.aligned.m8n8.x4.shared.b16 {%0,%1,%2,%3}, [%4];"
        : "=r"(r0), "=r"(r1), "=r"(r2), "=r"(r3) : "r"(a));
}

__device__ __forceinline__ void ldsm_x4_t(uint32_t& r0, uint32_t& r1,
                                          uint32_t& r2, uint32_t& r3, uint32_t a) {
    asm volatile("ldmatrix.sync.aligned.m8n8.x4.trans.shared.b16 {%0,%1,%2,%3}, [%4];"
        : "=r"(r0), "=r"(r1), "=r"(r2), "=r"(r3) : "r"(a));
}

__device__ __forceinline__ void mma_f16(float* c, const uint32_t* a, const uint32_t* b) {
    asm volatile(
        "mma.sync.aligned.m16n8k16.row.col.f32.f16.f16.f32 "
        "{%0,%1,%2,%3}, {%4,%5,%6,%7}, {%8,%9}, {%0,%1,%2,%3};"
        : "+f"(c[0]), "+f"(c[1]), "+f"(c[2]), "+f"(c[3])
        : "r"(a[0]), "r"(a[1]), "r"(a[2]), "r"(a[3]), "r"(b[0]), "r"(b[1]));
}

__device__ __forceinline__ uint32_t pkh(float a, float b) {
    __half2 t = __floats2half2_rn(a, b);
    return *reinterpret_cast<uint32_t*>(&t);
}

__device__ __forceinline__ uint32_t hex2(uint32_t h) {
    uint32_t r;
    asm("ex2.approx.f16x2 %0, %1;" : "=r"(r) : "r"(h));
    return r;
}

// ------------------- persistent mma.sync GEMM (plain fp16) -----------------
// C[M,N] = A[M,K] @ B[N,K]^T, fp32 accum. 256 thr / 8 warps, warp 32x64,
// CTA tile 128x128, 2 CTAs/SM, 3-stage cp.async ring, 1 barrier per chunk.
// PERSISTENT: grid-strided tile loop removes wave-quantization tails
// (768/1024-tile grids on 296 slots wasted 0.4-0.5 waves).
// Tile-top __syncthreads is required: chunk NK-1 occupies stage (NK-1)%3,
// which the next tile's prologue LOADC overwrites.
constexpr int GSTAGE    = 32768;                // A 16KB | B 16KB
constexpr int GEMM_SMEM = 3 * GSTAGE + 1024;    // 99328

template <int ACT, int OUTS>
__global__ void __launch_bounds__(256, 2) gemm_mma(
    const __half* __restrict__ Ah, const __half* __restrict__ Bh,
    const float* __restrict__ bias,
    float* __restrict__ C, __half* __restrict__ Ch,
    int Nx, int Kx, int qcols, int nbx, int ntiles)
{
    extern __shared__ char smraw[];
    const uint32_t sb0 = (smem_u32(smraw) + 1023u) & ~1023u;

    const int tid  = threadIdx.x;
    const int wid  = tid >> 5;
    const int lane = tid & 31;
    const int wm   = wid & 3;
    const int wn   = wid >> 2;
    const int NK   = Kx >> 6;

    const int lr = tid >> 1;
    const int lc = tid & 1;

    const uint32_t a_row   = (uint32_t)(wm * 32 + (lane & 15));
    const uint32_t a_mask  = (a_row & 7) << 4;
    const uint32_t a_inrow = ((uint32_t)lane >> 4) * 16;
    const uint32_t b_row   = (uint32_t)(wn * 64 + (lane & 7) + ((lane >> 4) << 3));
    const uint32_t b_mask  = (b_row & 7) << 4;
    const uint32_t b_inrow = (((uint32_t)lane >> 3) & 1) * 16;

#define LOADC(stg, kc) do {                                                   \
    uint32_t sb_ = sb0 + (uint32_t)(stg) * GSTAGE;                            \
    const char* pah = (const char*)(Ah + arow + (kc)) + lc * 64;              \
    const char* pbh = (const char*)(Bh + brow + (kc)) + lc * 64;              \
    _Pragma("unroll")                                                         \
    for (int j_ = 0; j_ < 4; ++j_) {                                          \
        uint32_t sw_ = swz128((uint32_t)(lr * 128 + lc * 64 + j_ * 16));      \
        cpasync16(sb_ +      0u + sw_, pah + j_ * 16);                        \
        cpasync16(sb_ + 16384u + sw_, pbh + j_ * 16);                        \
    }                                                                         \
    asm volatile("cp.async.commit_group;" ::: "memory");                      \
} while (0)

    for (int tile = blockIdx.x; tile < ntiles; tile += gridDim.x) {
        const int m0 = (tile / nbx) * 128;
        const int n0 = (tile % nbx) * 128;
        const size_t arow = (size_t)(m0 + lr) * Kx;
        const size_t brow = (size_t)(n0 + lr) * Kx;

        float acc[2][8][4] = {};

        __syncthreads();   // guard smem stage reuse across tiles
        LOADC(0, 0);
        LOADC(1, 64);

        int s_cmp = 0, s_ld = 2;

        for (int i = 0; i < NK; ++i) {
            if (i + 1 < NK) asm volatile("cp.async.wait_group 1;" ::: "memory");
            else            asm volatile("cp.async.wait_group 0;" ::: "memory");
            __syncthreads();

            if (i + 2 < NK) LOADC(s_ld, (i + 2) * 64);
            if (++s_ld == 3) s_ld = 0;

            const uint32_t sb = sb0 + (uint32_t)s_cmp * GSTAGE;
            if (++s_cmp == 3) s_cmp = 0;
            const uint32_t aB = sb + a_row * 128;
            const uint32_t bB = sb + 16384u + b_row * 128;

#pragma unroll
            for (int ks = 0; ks < 4; ++ks) {
                uint32_t ah[2][4], bh[8][2];
                const uint32_t ao = (a_inrow + ks * 32) ^ a_mask;
                const uint32_t bo = (b_inrow + ks * 32) ^ b_mask;
#pragma unroll
                for (int mi = 0; mi < 2; ++mi)
                    ldsm_x4(ah[mi][0], ah[mi][1], ah[mi][2], ah[mi][3],
                            aB + (uint32_t)mi * 2048 + ao);
#pragma unroll
                for (int j = 0; j < 4; ++j)
                    ldsm_x4(bh[2*j][0], bh[2*j][1], bh[2*j+1][0], bh[2*j+1][1],
                            bB + (uint32_t)j * 2048 + bo);
#pragma unroll
                for (int mi = 0; mi < 2; ++mi)
#pragma unroll
                    for (int nj = 0; nj < 8; ++nj)
                        mma_f16(acc[mi][nj], ah[mi], bh[nj]);
            }
        }

        const float sf = (n0 < qcols) ? QSCALE : 1.0f;

#pragma unroll
        for (int mi = 0; mi < 2; ++mi) {
            const int row0 = m0 + wm * 32 + mi * 16 + (lane >> 2);
#pragma unroll
            for (int nj = 0; nj < 8; ++nj) {
                const int col = n0 + wn * 64 + nj * 8 + (lane & 3) * 2;
                float v0 = acc[mi][nj][0], v1 = acc[mi][nj][1];
                float v2 = acc[mi][nj][2], v3 = acc[mi][nj][3];
                if (ACT >= 1) {
                    float2 bb = *(const float2*)&bias[col];
                    v0 += bb.x; v1 += bb.y; v2 += bb.x; v3 += bb.y;
                }
                if (ACT == 2) {
                    v0 = gelu_exact(v0); v1 = gelu_exact(v1);
                    v2 = gelu_exact(v2); v3 = gelu_exact(v3);
                }
                v0 *= sf; v1 *= sf; v2 *= sf; v3 *= sf;
                const size_t o0 = (size_t)row0 * Nx + col;
                const size_t o1 = (size_t)(row0 + 8) * Nx + col;
                if (OUTS == 0) {
                    *(float2*)&C[o0] = make_float2(v0, v1);
                    *(float2*)&C[o1] = make_float2(v2, v3);
                } else {
                    *(uint32_t*)&Ch[o0] = pkh(v0, v1);
                    *(uint32_t*)&Ch[o1] = pkh(v2, v3);
                }
            }
        }
    }
#undef LOADC
}

// --------------- persistent flash attention on mma.sync --------------------
// Work item: (head, q-tile of 128). 512 items, grid 296 (persistent).
// Head-major tile order: consecutive items on a CTA share the K/V stream
// in L2. Per-item state (Q load+hoist, acc, lacc) reset inside the loop.
constexpr int ASTAGE    = 16384;                 // K 8KB | V 8KB
constexpr int ATTN_SMEM = 16384 /*Q*/ + 2 * ASTAGE + 1024;
constexpr int ATILES    = (S / 128) * Bv * H;    // 512

__global__ void __launch_bounds__(256, 2) attn_mma(
    const __half* __restrict__ qkvh,
    const uint32_t* __restrict__ pm,
    __half* __restrict__ oh)
{
    extern __shared__ char smraw[];
    const uint32_t sbQ = (smem_u32(smraw) + 1023u) & ~1023u;
    const uint32_t sbKV0 = sbQ + 16384u;

    const int tid  = threadIdx.x;
    const int wid  = tid >> 5;
    const int lane = tid & 31;

    const uint32_t a_row   = (uint32_t)(wid * 16 + (lane & 15));
    const uint32_t a_mask  = (a_row & 7) << 4;
    const uint32_t a_inrow = ((uint32_t)lane >> 4) * 16;
    const uint32_t qAh = sbQ + a_row * 128;

    const uint32_t b_row   = (uint32_t)((lane & 7) + ((lane >> 4) << 3));
    const uint32_t b_mask  = (b_row & 7) << 4;
    const uint32_t b_inrow = (((uint32_t)lane >> 3) & 1) * 16;

    const uint32_t v_rowl  = (uint32_t)(lane & 15);
    const uint32_t v_byte  = ((uint32_t)lane >> 4) * 16;

    const uint32_t ones2[2] = {0x3C003C00u, 0x3C003C00u};
    constexpr int NT = S / 64;

#define LOADKV(stg, kb) do {                                                  \
    uint32_t sb_ = sbKV0 + (uint32_t)(stg) * ASTAGE;                          \
    const size_t roff_ = (size_t)(b * S + (kb) + kvrow) * QS;                 \
    const char* pkh_ = (const char*)(kh_p + roff_);                           \
    const char* pvh_ = (const char*)(vh_p + roff_);                           \
    _Pragma("unroll")                                                         \
    for (int c_ = 0; c_ < 2; ++c_) {                                          \
        uint32_t off_ = (uint32_t)(kvc * 16 + c_ * 64);                       \
        uint32_t sw_  = swz128((uint32_t)(kvrow * 128) + off_);               \
        cpasync16(sb_ +    0u + sw_, pkh_ + off_);                            \
        cpasync16(sb_ + 8192u + sw_, pvh_ + off_);                            \
    }                                                                         \
    asm volatile("cp.async.commit_group;" ::: "memory");                      \
} while (0)

    const int kvrow = tid >> 2;
    const int kvc   = tid & 3;

    for (int tile = blockIdx.x; tile < ATILES; tile += gridDim.x) {
        const int bh_ = tile >> 4;          // head-major
        const int qi  = tile & 15;
        const int b   = bh_ >> 4;
        const int h   = bh_ & 15;
        const int q0  = qi * 128;

        const __half* qh_p = qkvh + (size_t)h * HD;
        const __half* kh_p = qkvh + 1024 + (size_t)h * HD;
        const __half* vh_p = qkvh + 2048 + (size_t)h * HD;

        __syncthreads();   // guard smem reuse across work items

        // ---- Q tile load ----
        {
            const int row  = tid >> 1;
            const int half = tid & 1;
            const size_t src = (size_t)(b * S + q0 + row) * QS;
            const char* pqh = (const char*)(qh_p + src) + half * 64;
#pragma unroll
            for (int j = 0; j < 4; ++j) {
                uint32_t sw = swz128((uint32_t)(row * 128 + half * 64 + j * 16));
                cpasync16(sbQ + sw, pqh + j * 16);
            }
        }
        LOADKV(0, 0);   // group 0 also carries the Q loads

        float acc[8][4] = {};
        float lacc[4]   = {};

        const int r0 = q0 + wid * 16 + (lane >> 2);
        const int r1 = r0 + 8;

        asm volatile("cp.async.wait_group 0;" ::: "memory");
        __syncthreads();
        uint32_t qa[4][4];
#pragma unroll
        for (int ks = 0; ks < 4; ++ks) {
            const uint32_t ao = (a_inrow + ks * 32) ^ a_mask;
            ldsm_x4(qa[ks][0], qa[ks][1], qa[ks][2], qa[ks][3], qAh + ao);
        }

        for (int it = 0; it < NT; ++it) {
            if (it) {
                asm volatile("cp.async.wait_group 0;" ::: "memory");
                __syncthreads();
            }
            if (it + 1 < NT) LOADKV((it + 1) & 1, (it + 1) * 64);

            const uint32_t sb = sbKV0 + (uint32_t)(it & 1) * ASTAGE;
            const uint32_t kB = sb + b_row * 128;

            float sc[8][4] = {};
#pragma unroll
            for (int ks = 0; ks < 4; ++ks) {
                uint32_t kbh[8][2];
                const uint32_t bo = (b_inrow + ks * 32) ^ b_mask;
#pragma unroll
                for (int j = 0; j < 4; ++j)
                    ldsm_x4(kbh[2*j][0], kbh[2*j][1], kbh[2*j+1][0], kbh[2*j+1][1],
                            kB + (uint32_t)j * 2048 + bo);
#pragma unroll
                for (int j = 0; j < 8; ++j)
                    mma_f16(sc[j], qa[ks], kbh[j]);
            }

            const uint32_t w0a = pm[(size_t)r0 * 64 + it * 2];
            const uint32_t w0b = pm[(size_t)r0 * 64 + it * 2 + 1];
            const uint32_t w1a = pm[(size_t)r1 * 64 + it * 2];
            const uint32_t w1b = pm[(size_t)r1 * 64 + it * 2 + 1];
            uint32_t p01[8], p23[8];
#pragma unroll
            for (int j = 0; j < 8; ++j) {
                const int cl    = j * 8 + (lane & 3) * 2;
                const int shift = cl & 31;
                const uint32_t bits0 = ((cl & 32) ? w0b : w0a) >> shift;
                const uint32_t bits1 = ((cl & 32) ? w1b : w1a) >> shift;
                float s0 = (bits0 & 1u) ? -30000.f : sc[j][0];
                float s1 = (bits0 & 2u) ? -30000.f : sc[j][1];
                float s2 = (bits1 & 1u) ? -30000.f : sc[j][2];
                float s3 = (bits1 & 2u) ? -30000.f : sc[j][3];
                p01[j] = hex2(pkh(s0, s1));
                p23[j] = hex2(pkh(s2, s3));
            }

#pragma unroll
            for (int ks = 0; ks < 4; ++ks) {
                uint32_t pah[4];
                pah[0] = p01[2*ks];
                pah[1] = p23[2*ks];
                pah[2] = p01[2*ks+1];
                pah[3] = p23[2*ks+1];

                const uint32_t vrow = (uint32_t)(ks * 16) + v_rowl;
                const uint32_t vB   = sb + vrow * 128;
                const uint32_t vmsk = (vrow & 7) << 4;
                uint32_t vbh[8][2];
#pragma unroll
                for (int dp = 0; dp < 4; ++dp) {
                    const uint32_t vo = (v_byte + (uint32_t)dp * 32) ^ vmsk;
                    ldsm_x4_t(vbh[2*dp][0], vbh[2*dp][1], vbh[2*dp+1][0], vbh[2*dp+1][1],
                              vB + 8192u + vo);
                }
#pragma unroll
                for (int j = 0; j < 8; ++j)
                    mma_f16(acc[j], pah, vbh[j]);
                mma_f16(lacc, pah, ones2);
            }
        }

        const float inv0 = 1.0f / lacc[0];
        const float inv1 = 1.0f / lacc[2];
        const size_t go0 = (size_t)(b * S + r0) * D + h * HD;
        const size_t go1 = (size_t)(b * S + r1) * D + h * HD;
#pragma unroll
        for (int j = 0; j < 8; ++j) {
            const int col = j * 8 + (lane & 3) * 2;
            *(uint32_t*)&oh[go0 + col] = pkh(acc[j][0] * inv0, acc[j][1] * inv0);
            *(uint32_t*)&oh[go1 + col] = pkh(acc[j][2] * inv1, acc[j][3] * inv1);
        }
    }
#undef LOADKV
}

// ------------------------- fused prep megakernel ---------------------------
constexpr int PREP_BLOCKS = 17408;

__device__ __forceinline__ void tcvt_body(
    float (*t)[33], const float* __restrict__ W, __half* __restrict__ T,
    int K, int N, int bx, int by, int tid)
{
    const int n0 = bx * 32;
    const int k0 = by * 32;
    const int lx = tid & 31;
    const int ly = tid >> 5;
#pragma unroll
    for (int j = 0; j < 4; ++j)
        t[ly + j * 8][lx] = W[(size_t)(k0 + ly + j * 8) * N + n0 + lx];
    __syncthreads();
#pragma unroll
    for (int e = 0; e < 2; ++e) {
        const int idx = tid + e * 256;
        const int row = idx >> 4;
        const int kp  = (idx & 15) * 2;
        const uint32_t hv = pkh(t[kp][row], t[kp + 1][row]);
        *(uint32_t*)&T[(size_t)(n0 + row) * K + k0 + kp] = hv;
    }
}

__global__ void __launch_bounds__(256) prep_all(
    const float* __restrict__ Wq, const float* __restrict__ Wk,
    const float* __restrict__ Wv, const float* __restrict__ Wo,
    const float* __restrict__ W1, const float* __restrict__ W2,
    const float* __restrict__ x, const int* __restrict__ mask,
    __half* __restrict__ wqkvoh, __half* __restrict__ w1h,
    __half* __restrict__ w2h, __half* __restrict__ xh,
    uint16_t* __restrict__ pmh)
{
    __shared__ float t[32][33];
    const int bid = blockIdx.x;
    const int tid = threadIdx.x;

    if (bid < 4096) {
        const int z   = bid >> 10;
        const int rem = bid & 1023;
        const float* W = (z == 0) ? Wq : (z == 1) ? Wk : (z == 2) ? Wv : Wo;
        tcvt_body(t, W, wqkvoh + (size_t)z * D * D, D, D,
                  rem & 31, rem >> 5, tid);
    } else if (bid < 8192) {
        const int rem = bid - 4096;
        tcvt_body(t, W1, w1h, D, DFF, rem & 127, rem >> 7, tid);
    } else if (bid < 12288) {
        const int rem = bid - 8192;
        tcvt_body(t, W2, w2h, DFF, D, rem & 31, rem >> 5, tid);
    } else if (bid < 13312) {
        const int hi = (bid - 12288) * 256 + tid;
        const int4* p = (const int4*)(mask + (size_t)hi * 16);
        uint32_t bits = 0;
#pragma unroll
        for (int j = 0; j < 4; ++j) {
            int4 v = p[j];
            bits |= (uint32_t)(v.x == 1) << (4 * j);
            bits |= (uint32_t)(v.y == 1) << (4 * j + 1);
            bits |= (uint32_t)(v.z == 1) << (4 * j + 2);
            bits |= (uint32_t)(v.w == 1) << (4 * j + 3);
        }
        pmh[hi] = (uint16_t)bits;
    } else {
        const int i = (bid - 13312) * 256 + tid;
        float4 v = ((const float4*)x)[i];
        uint2 hp;
        hp.x = pkh(v.x, v.y); hp.y = pkh(v.z, v.w);
        ((uint2*)xh)[i] = hp;
    }
}

// ---------------- residual + layernorm ------------------------------------
template <int X16, int OUT32>
__global__ void __launch_bounds__(256) ln_res_kernel(
    const float* __restrict__ xres32, const __half* __restrict__ xres16,
    const __half* __restrict__ a,
    const float* __restrict__ g, const float* __restrict__ beta,
    float* __restrict__ out, __half* __restrict__ outh)
{
    const int row = blockIdx.x;
    const int tid = threadIdx.x;
    const uint2 araw = *(const uint2*)&a[(long)row * D + tid * 4];
    const __half2 a01 = *reinterpret_cast<const __half2*>(&araw.x);
    const __half2 a23 = *reinterpret_cast<const __half2*>(&araw.y);
    float4 v;
    v.x = __low2float(a01);  v.y = __high2float(a01);
    v.z = __low2float(a23);  v.w = __high2float(a23);

    float s  = v.x + v.y + v.z + v.w;
    float ss = v.x * v.x + v.y * v.y + v.z * v.z + v.w * v.w;
#pragma unroll
    for (int off = 16; off; off >>= 1) {
        s  += __shfl_xor_sync(0xffffffffu, s,  off);
        ss += __shfl_xor_sync(0xffffffffu, ss, off);
    }
    __shared__ float sbuf[8], ssbuf[8];
    __shared__ float mean_s, rstd_s;
    const int warp = tid >> 5;
    if ((tid & 31) == 0) { sbuf[warp] = s; ssbuf[warp] = ss; }
    __syncthreads();
    if (tid == 0) {
        float t = 0.f, ts = 0.f;
#pragma unroll
        for (int w = 0; w < 8; ++w) { t += sbuf[w]; ts += ssbuf[w]; }
        float mean = t * (1.0f / D);
        float var  = ts * (1.0f / D) - mean * mean;
        mean_s = mean;
        rstd_s = rsqrtf(var + 1e-5f);
    }
    __syncthreads();
    const float mean = mean_s, rstd = rstd_s;

    float4 gv = *(const float4*)&g[tid * 4];
    float4 bv = *(const float4*)&beta[tid * 4];
    float4 xr;
    if (X16) {
        const uint2 xraw = *(const uint2*)&xres16[(long)row * D + tid * 4];
        const __half2 x01 = *reinterpret_cast<const __half2*>(&xraw.x);
        const __half2 x23 = *reinterpret_cast<const __half2*>(&xraw.y);
        xr.x = __low2float(x01);  xr.y = __high2float(x01);
        xr.z = __low2float(x23);  xr.w = __high2float(x23);
    } else {
        xr = *(const float4*)&xres32[(long)row * D + tid * 4];
    }
    float4 ov;
    ov.x = xr.x + (v.x - mean) * rstd * gv.x + bv.x;
    ov.y = xr.y + (v.y - mean) * rstd * gv.y + bv.y;
    ov.z = xr.z + (v.z - mean) * rstd * gv.z + bv.z;
    ov.w = xr.w + (v.w - mean) * rstd * gv.w + bv.w;
    if (OUT32) {
        *(float4*)&out[(long)row * D + tid * 4] = ov;
    } else {
        uint2 hp;
        hp.x = pkh(ov.x, ov.y); hp.y = pkh(ov.z, ov.w);
        *(uint2*)&outh[(long)row * D + tid * 4] = hp;
    }
}

// ---------------------------------------------------------------------------
extern "C" void kernel_launch(void* const* d_in, const int* in_sizes, int n_in,
                              void* d_out, int out_size)
{
    const float* x    = (const float*)d_in[0];
    const int*   mask = (const int*)  d_in[1];
    const float* Wq   = (const float*)d_in[2];
    const float* Wk   = (const float*)d_in[3];
    const float* Wv   = (const float*)d_in[4];
    const float* Wo   = (const float*)d_in[5];
    const float* bo   = (const float*)d_in[6];
    const float* ln1g = (const float*)d_in[7];
    const float* ln1b = (const float*)d_in[8];
    const float* W1   = (const float*)d_in[9];
    const float* b1   = (const float*)d_in[10];
    const float* W2   = (const float*)d_in[11];
    const float* b2   = (const float*)d_in[12];
    const float* ln2g = (const float*)d_in[13];
    const float* ln2b = (const float*)d_in[14];
    float* out = (float*)d_out;

    uint32_t* pm;
    cudaGetSymbolAddress((void**)&pm, g_pm);

    __half *xh, *qkvh, *oh, *t0h, *x1h, *hh, *h2h;
    __half *wqkvoh, *w1h, *w2h;
    cudaGetSymbolAddress((void**)&xh,    g_xh);
    cudaGetSymbolAddress((void**)&qkvh,  g_qkvh);
    cudaGetSymbolAddress((void**)&oh,    g_oh);
    cudaGetSymbolAddress((void**)&t0h,   g_t0h);
    cudaGetSymbolAddress((void**)&x1h,   g_x1h);
    cudaGetSymbolAddress((void**)&hh,    g_hh);
    cudaGetSymbolAddress((void**)&h2h,   g_h2h);
    cudaGetSymbolAddress((void**)&wqkvoh, g_wqkvoh);
    cudaGetSymbolAddress((void**)&w1h,   g_w1h);
    cudaGetSymbolAddress((void**)&w2h,   g_w2h);

    __half* woh = wqkvoh + (size_t)3 * D * D;

    cudaFuncSetAttribute(attn_mma, cudaFuncAttributeMaxDynamicSharedMemorySize, ATTN_SMEM);
    cudaFuncSetAttribute(gemm_mma<0,1>, cudaFuncAttributeMaxDynamicSharedMemorySize, GEMM_SMEM);
    cudaFuncSetAttribute(gemm_mma<1,1>, cudaFuncAttributeMaxDynamicSharedMemorySize, GEMM_SMEM);
    cudaFuncSetAttribute(gemm_mma<2,1>, cudaFuncAttributeMaxDynamicSharedMemorySize, GEMM_SMEM);

    // ALL prep in ONE launch
    prep_all<<<PREP_BLOCKS, 256>>>(Wq, Wk, Wv, Wo, W1, W2, x, mask,
                                   wqkvoh, w1h, w2h, xh, (uint16_t*)pm);

    // fused QKV projection (persistent): 768 tiles, nbx=24
    {
        const int nt = (QS / 128) * (M / 128);
        gemm_mma<0,1><<<(nt < NSM_SLOTS ? nt : NSM_SLOTS), 256, GEMM_SMEM>>>(
            xh, wqkvoh, nullptr, nullptr, qkvh, QS, D, 1024, QS / 128, nt);
    }

    // flash attention (persistent): 512 items
    attn_mma<<<(ATILES < NSM_SLOTS ? ATILES : NSM_SLOTS), 256, ATTN_SMEM>>>(
        qkvh, pm, oh);

    // output projection + bias -> fp16 t0h: 256 tiles
    {
        const int nt = (D / 128) * (M / 128);
        gemm_mma<1,1><<<(nt < NSM_SLOTS ? nt : NSM_SLOTS), 256, GEMM_SMEM>>>(
            oh, woh, bo, nullptr, t0h, D, D, 0, D / 128, nt);
    }

    // x1 = x + LN(attn_out) -> fp16 only
    ln_res_kernel<0,0><<<M, 256>>>(x, nullptr, t0h, ln1g, ln1b, nullptr, x1h);

    // FFN (persistent)
    {
        const int nt = (DFF / 128) * (M / 128);   // 1024
        gemm_mma<2,1><<<(nt < NSM_SLOTS ? nt : NSM_SLOTS), 256, GEMM_SMEM>>>(
            x1h, w1h, b1, nullptr, hh, DFF, D, 0, DFF / 128, nt);
    }
    {
        const int nt = (D / 128) * (M / 128);     // 256
        gemm_mma<2,1><<<(nt < NSM_SLOTS ? nt : NSM_SLOTS), 256, GEMM_SMEM>>>(
            hh, w2h, b2, nullptr, h2h, D, DFF, 0, D / 128, nt);
    }

    // out = x1 + LN(h2), fp16 residual -> fp32 out
    ln_res_kernel<1,1><<<M, 256>>>(nullptr, x1h, h2h, ln2g, ln2b, out, nullptr);
}

// round 15
// speedup vs baseline: 1.0336x; 1.0336x over previous
#include <cuda_runtime.h>
#include <cuda_fp16.h>
#include <math.h>
#include <cstdint>
#include <cstddef>

// ------------------------- problem constants -------------------------------
constexpr int Bv   = 2;
constexpr int S    = 2048;
constexpr int D    = 1024;
constexpr int H    = 16;
constexpr int HD   = 64;
constexpr int M    = Bv * S;      // 4096
constexpr int DFF  = 4 * D;       // 4096
constexpr int QS   = 3 * D;       // fused qkv row stride 3072

// 0.125 * log2(e): folded into Q at projection so scores are exp2-ready.
constexpr float QSCALE = 0.18033688011f;

// ------------------------- scratch (device globals) ------------------------
__device__ uint32_t g_pm[S * (S / 32)];       // bit-packed mask

__device__ __half g_xh  [M * D];
__device__ __half g_qkvh[(size_t)M * QS];
__device__ __half g_oh  [M * D];
__device__ __half g_t0h [M * D];
__device__ __half g_x1h [M * D];
__device__ __half g_hh  [(size_t)M * DFF];
__device__ __half g_h2h [M * D];
__device__ __half g_wqkvoh[(size_t)4 * D * D];   // Wq|Wk|Wv|Wo transposed
__device__ __half g_w1h[(size_t)D * DFF];
__device__ __half g_w2h[(size_t)D * DFF];

// ------------------------- small helpers -----------------------------------
__device__ __forceinline__ float gelu_exact(float x) {
    return 0.5f * x * (1.0f + erff(x * 0.70710678118654752f));
}

__device__ __forceinline__ uint32_t smem_u32(const void* p) {
    uint32_t a;
    asm("{ .reg .u64 t; cvta.to.shared.u64 t, %1; cvt.u32.u64 %0, t; }"
        : "=r"(a) : "l"(p));
    return a;
}

__device__ __forceinline__ uint32_t swz128(uint32_t x) {
    return x ^ ((x >> 3) & 0x70);
}

__device__ __forceinline__ void cpasync16(uint32_t dst, const void* src) {
    asm volatile("cp.async.cg.shared.global [%0], [%1], 16;" :: "r"(dst), "l"(src));
}

__device__ __forceinline__ void ldsm_x4(uint32_t& r0, uint32_t& r1,
                                        uint32_t& r2, uint32_t& r3, uint32_t a) {
    asm volatile("ldmatrix.sync.aligned.m8n8.x4.shared.b16 {%0,%1,%2,%3}, [%4];"
        : "=r"(r0), "=r"(r1), "=r"(r2), "=r"(r3) : "r"(a));
}

__device__ __forceinline__ void ldsm_x4_t(uint32_t& r0, uint32_t& r1,
                                          uint32_t& r2, uint32_t& r3, uint32_t a) {
    asm volatile("ldmatrix.sync.aligned.m8n8.x4.trans.shared.b16 {%0,%1,%2,%3}, [%4];"
        : "=r"(r0), "=r"(r1), "=r"(r2), "=r"(r3) : "r"(a));
}

__device__ __forceinline__ void mma_f16(float* c, const uint32_t* a, const uint32_t* b) {
    asm volatile(
        "mma.sync.aligned.m16n8k16.row.col.f32.f16.f16.f32 "
        "{%0,%1,%2,%3}, {%4,%5,%6,%7}, {%8,%9}, {%0,%1,%2,%3};"
        : "+f"(c[0]), "+f"(c[1]), "+f"(c[2]), "+f"(c[3])
        : "r"(a[0]), "r"(a[1]), "r"(a[2]), "r"(a[3]), "r"(b[0]), "r"(b[1]));
}

__device__ __forceinline__ uint32_t pkh(float a, float b) {
    __half2 t = __floats2half2_rn(a, b);
    return *reinterpret_cast<uint32_t*>(&t);
}

__device__ __forceinline__ uint32_t hex2(uint32_t h) {
    uint32_t r;
    asm("ex2.approx.f16x2 %0, %1;" : "=r"(r) : "r"(h));
    return r;
}

// ------------------------- mma.sync GEMM (plain fp16) ----------------------
// R13 form (non-persistent: R14's persistent tile loop regressed).
// C[M,N] = A[M,K] @ B[N,K]^T, fp32 accum. 256 thr / 8 warps, warp 32x64,
// CTA 128x128, 2 CTAs/SM. 3-stage cp.async ring, one barrier per K-chunk.
// qcols: output cols < qcols are scaled by QSCALE (QKV launch: q columns).
constexpr int GSTAGE    = 32768;                // A 16KB | B 16KB
constexpr int GEMM_SMEM = 3 * GSTAGE + 1024;    // 99328

template <int ACT, int OUTS>
__global__ void __launch_bounds__(256, 2) gemm_mma(
    const __half* __restrict__ Ah, const __half* __restrict__ Bh,
    const float* __restrict__ bias,
    float* __restrict__ C, __half* __restrict__ Ch,
    int Nx, int Kx, int qcols)
{
    extern __shared__ char smraw[];
    const uint32_t sb0 = (smem_u32(smraw) + 1023u) & ~1023u;

    const int tid  = threadIdx.x;
    const int wid  = tid >> 5;
    const int lane = tid & 31;
    const int m0   = blockIdx.y * 128;
    const int n0   = blockIdx.x * 128;
    const int wm   = wid & 3;
    const int wn   = wid >> 2;
    const int NK   = Kx >> 6;

    const int lr = tid >> 1;
    const int lc = tid & 1;
    const size_t arow = (size_t)(m0 + lr) * Kx;
    const size_t brow = (size_t)(n0 + lr) * Kx;

#define LOADC(stg, kc) do {                                                   \
    uint32_t sb_ = sb0 + (uint32_t)(stg) * GSTAGE;                            \
    const char* pah = (const char*)(Ah + arow + (kc)) + lc * 64;              \
    const char* pbh = (const char*)(Bh + brow + (kc)) + lc * 64;              \
    _Pragma("unroll")                                                         \
    for (int j_ = 0; j_ < 4; ++j_) {                                          \
        uint32_t sw_ = swz128((uint32_t)(lr * 128 + lc * 64 + j_ * 16));      \
        cpasync16(sb_ +      0u + sw_, pah + j_ * 16);                        \
        cpasync16(sb_ + 16384u + sw_, pbh + j_ * 16);                        \
    }                                                                         \
    asm volatile("cp.async.commit_group;" ::: "memory");                      \
} while (0)

    const uint32_t a_row   = (uint32_t)(wm * 32 + (lane & 15));
    const uint32_t a_mask  = (a_row & 7) << 4;
    const uint32_t a_inrow = ((uint32_t)lane >> 4) * 16;
    const uint32_t b_row   = (uint32_t)(wn * 64 + (lane & 7) + ((lane >> 4) << 3));
    const uint32_t b_mask  = (b_row & 7) << 4;
    const uint32_t b_inrow = (((uint32_t)lane >> 3) & 1) * 16;

    float acc[2][8][4] = {};

    LOADC(0, 0);
    LOADC(1, 64);

    int s_cmp = 0, s_ld = 2;

    for (int i = 0; i < NK; ++i) {
        if (i + 1 < NK) asm volatile("cp.async.wait_group 1;" ::: "memory");
        else            asm volatile("cp.async.wait_group 0;" ::: "memory");
        __syncthreads();

        if (i + 2 < NK) LOADC(s_ld, (i + 2) * 64);
        if (++s_ld == 3) s_ld = 0;

        const uint32_t sb = sb0 + (uint32_t)s_cmp * GSTAGE;
        if (++s_cmp == 3) s_cmp = 0;
        const uint32_t aB = sb + a_row * 128;
        const uint32_t bB = sb + 16384u + b_row * 128;

#pragma unroll
        for (int ks = 0; ks < 4; ++ks) {
            uint32_t ah[2][4], bh[8][2];
            const uint32_t ao = (a_inrow + ks * 32) ^ a_mask;
            const uint32_t bo = (b_inrow + ks * 32) ^ b_mask;
#pragma unroll
            for (int mi = 0; mi < 2; ++mi)
                ldsm_x4(ah[mi][0], ah[mi][1], ah[mi][2], ah[mi][3],
                        aB + (uint32_t)mi * 2048 + ao);
#pragma unroll
            for (int j = 0; j < 4; ++j)
                ldsm_x4(bh[2*j][0], bh[2*j][1], bh[2*j+1][0], bh[2*j+1][1],
                        bB + (uint32_t)j * 2048 + bo);
#pragma unroll
            for (int mi = 0; mi < 2; ++mi)
#pragma unroll
                for (int nj = 0; nj < 8; ++nj)
                    mma_f16(acc[mi][nj], ah[mi], bh[nj]);
        }
    }

    const float sf = (n0 < qcols) ? QSCALE : 1.0f;

#pragma unroll
    for (int mi = 0; mi < 2; ++mi) {
        const int row0 = m0 + wm * 32 + mi * 16 + (lane >> 2);
#pragma unroll
        for (int nj = 0; nj < 8; ++nj) {
            const int col = n0 + wn * 64 + nj * 8 + (lane & 3) * 2;
            float v0 = acc[mi][nj][0], v1 = acc[mi][nj][1];
            float v2 = acc[mi][nj][2], v3 = acc[mi][nj][3];
            if (ACT >= 1) {
                float2 bb = *(const float2*)&bias[col];
                v0 += bb.x; v1 += bb.y; v2 += bb.x; v3 += bb.y;
            }
            if (ACT == 2) {
                v0 = gelu_exact(v0); v1 = gelu_exact(v1);
                v2 = gelu_exact(v2); v3 = gelu_exact(v3);
            }
            v0 *= sf; v1 *= sf; v2 *= sf; v3 *= sf;
            const size_t o0 = (size_t)row0 * Nx + col;
            const size_t o1 = (size_t)(row0 + 8) * Nx + col;
            if (OUTS == 0) {
                *(float2*)&C[o0] = make_float2(v0, v1);
                *(float2*)&C[o1] = make_float2(v2, v3);
            } else {
                *(uint32_t*)&Ch[o0] = pkh(v0, v1);
                *(uint32_t*)&Ch[o1] = pkh(v2, v3);
            }
        }
    }
#undef LOADC
}

// --------------- flash attention, balanced 2-tile persistence --------------
// 512 work items on grid 256: EXACTLY 2 tiles per CTA (R14's 296-grid gave
// an imbalanced 2-vs-1 split; balanced removes the 80 idle slots in round 2).
// Everything else identical to the validated R13/R14 attention body.
constexpr int ASTAGE    = 16384;                 // K 8KB | V 8KB
constexpr int ATTN_SMEM = 16384 /*Q*/ + 2 * ASTAGE + 1024;
constexpr int ATILES    = (S / 128) * Bv * H;    // 512
constexpr int AGRID     = ATILES / 2;            // 256

__global__ void __launch_bounds__(256, 2) attn_mma(
    const __half* __restrict__ qkvh,
    const uint32_t* __restrict__ pm,
    __half* __restrict__ oh)
{
    extern __shared__ char smraw[];
    const uint32_t sbQ = (smem_u32(smraw) + 1023u) & ~1023u;
    const uint32_t sbKV0 = sbQ + 16384u;

    const int tid  = threadIdx.x;
    const int wid  = tid >> 5;
    const int lane = tid & 31;

    const uint32_t a_row   = (uint32_t)(wid * 16 + (lane & 15));
    const uint32_t a_mask  = (a_row & 7) << 4;
    const uint32_t a_inrow = ((uint32_t)lane >> 4) * 16;
    const uint32_t qAh = sbQ + a_row * 128;

    const uint32_t b_row   = (uint32_t)((lane & 7) + ((lane >> 4) << 3));
    const uint32_t b_mask  = (b_row & 7) << 4;
    const uint32_t b_inrow = (((uint32_t)lane >> 3) & 1) * 16;

    const uint32_t v_rowl  = (uint32_t)(lane & 15);
    const uint32_t v_byte  = ((uint32_t)lane >> 4) * 16;

    const uint32_t ones2[2] = {0x3C003C00u, 0x3C003C00u};
    constexpr int NT = S / 64;

    const int kvrow = tid >> 2;
    const int kvc   = tid & 3;

#define LOADKV(stg, kb) do {                                                  \
    uint32_t sb_ = sbKV0 + (uint32_t)(stg) * ASTAGE;                          \
    const size_t roff_ = (size_t)(b * S + (kb) + kvrow) * QS;                 \
    const char* pkh_ = (const char*)(kh_p + roff_);                           \
    const char* pvh_ = (const char*)(vh_p + roff_);                           \
    _Pragma("unroll")                                                         \
    for (int c_ = 0; c_ < 2; ++c_) {                                          \
        uint32_t off_ = (uint32_t)(kvc * 16 + c_ * 64);                       \
        uint32_t sw_  = swz128((uint32_t)(kvrow * 128) + off_);               \
        cpasync16(sb_ +    0u + sw_, pkh_ + off_);                            \
        cpasync16(sb_ + 8192u + sw_, pvh_ + off_);                            \
    }                                                                         \
    asm volatile("cp.async.commit_group;" ::: "memory");                      \
} while (0)

#pragma unroll 1
    for (int tile = blockIdx.x; tile < ATILES; tile += AGRID) {
        const int bh_ = tile >> 4;          // head-major
        const int qi  = tile & 15;
        const int b   = bh_ >> 4;
        const int h   = bh_ & 15;
        const int q0  = qi * 128;

        const __half* qh_p = qkvh + (size_t)h * HD;
        const __half* kh_p = qkvh + 1024 + (size_t)h * HD;
        const __half* vh_p = qkvh + 2048 + (size_t)h * HD;

        __syncthreads();   // guard smem reuse across the two work items

        // ---- Q tile load ----
        {
            const int row  = tid >> 1;
            const int half = tid & 1;
            const size_t src = (size_t)(b * S + q0 + row) * QS;
            const char* pqh = (const char*)(qh_p + src) + half * 64;
#pragma unroll
            for (int j = 0; j < 4; ++j) {
                uint32_t sw = swz128((uint32_t)(row * 128 + half * 64 + j * 16));
                cpasync16(sbQ + sw, pqh + j * 16);
            }
        }
        LOADKV(0, 0);   // group 0 also carries the Q loads

        float acc[8][4] = {};
        float lacc[4]   = {};

        const int r0 = q0 + wid * 16 + (lane >> 2);
        const int r1 = r0 + 8;

        asm volatile("cp.async.wait_group 0;" ::: "memory");
        __syncthreads();
        uint32_t qa[4][4];
#pragma unroll
        for (int ks = 0; ks < 4; ++ks) {
            const uint32_t ao = (a_inrow + ks * 32) ^ a_mask;
            ldsm_x4(qa[ks][0], qa[ks][1], qa[ks][2], qa[ks][3], qAh + ao);
        }

        for (int it = 0; it < NT; ++it) {
            if (it) {
                asm volatile("cp.async.wait_group 0;" ::: "memory");
                __syncthreads();
            }
            if (it + 1 < NT) LOADKV((it + 1) & 1, (it + 1) * 64);

            const uint32_t sb = sbKV0 + (uint32_t)(it & 1) * ASTAGE;
            const uint32_t kB = sb + b_row * 128;

            float sc[8][4] = {};
#pragma unroll
            for (int ks = 0; ks < 4; ++ks) {
                uint32_t kbh[8][2];
                const uint32_t bo = (b_inrow + ks * 32) ^ b_mask;
#pragma unroll
                for (int j = 0; j < 4; ++j)
                    ldsm_x4(kbh[2*j][0], kbh[2*j][1], kbh[2*j+1][0], kbh[2*j+1][1],
                            kB + (uint32_t)j * 2048 + bo);
#pragma unroll
                for (int j = 0; j < 8; ++j)
                    mma_f16(sc[j], qa[ks], kbh[j]);
            }

            const uint32_t w0a = pm[(size_t)r0 * 64 + it * 2];
            const uint32_t w0b = pm[(size_t)r0 * 64 + it * 2 + 1];
            const uint32_t w1a = pm[(size_t)r1 * 64 + it * 2];
            const uint32_t w1b = pm[(size_t)r1 * 64 + it * 2 + 1];
            uint32_t p01[8], p23[8];
#pragma unroll
            for (int j = 0; j < 8; ++j) {
                const int cl    = j * 8 + (lane & 3) * 2;
                const int shift = cl & 31;
                const uint32_t bits0 = ((cl & 32) ? w0b : w0a) >> shift;
                const uint32_t bits1 = ((cl & 32) ? w1b : w1a) >> shift;
                float s0 = (bits0 & 1u) ? -30000.f : sc[j][0];
                float s1 = (bits0 & 2u) ? -30000.f : sc[j][1];
                float s2 = (bits1 & 1u) ? -30000.f : sc[j][2];
                float s3 = (bits1 & 2u) ? -30000.f : sc[j][3];
                p01[j] = hex2(pkh(s0, s1));
                p23[j] = hex2(pkh(s2, s3));
            }

#pragma unroll
            for (int ks = 0; ks < 4; ++ks) {
                uint32_t pah[4];
                pah[0] = p01[2*ks];
                pah[1] = p23[2*ks];
                pah[2] = p01[2*ks+1];
                pah[3] = p23[2*ks+1];

                const uint32_t vrow = (uint32_t)(ks * 16) + v_rowl;
                const uint32_t vB   = sb + vrow * 128;
                const uint32_t vmsk = (vrow & 7) << 4;
                uint32_t vbh[8][2];
#pragma unroll
                for (int dp = 0; dp < 4; ++dp) {
                    const uint32_t vo = (v_byte + (uint32_t)dp * 32) ^ vmsk;
                    ldsm_x4_t(vbh[2*dp][0], vbh[2*dp][1], vbh[2*dp+1][0], vbh[2*dp+1][1],
                              vB + 8192u + vo);
                }
#pragma unroll
                for (int j = 0; j < 8; ++j)
                    mma_f16(acc[j], pah, vbh[j]);
                mma_f16(lacc, pah, ones2);
            }
        }

        const float inv0 = 1.0f / lacc[0];
        const float inv1 = 1.0f / lacc[2];
        const size_t go0 = (size_t)(b * S + r0) * D + h * HD;
        const size_t go1 = (size_t)(b * S + r1) * D + h * HD;
#pragma unroll
        for (int j = 0; j < 8; ++j) {
            const int col = j * 8 + (lane & 3) * 2;
            *(uint32_t*)&oh[go0 + col] = pkh(acc[j][0] * inv0, acc[j][1] * inv0);
            *(uint32_t*)&oh[go1 + col] = pkh(acc[j][2] * inv1, acc[j][3] * inv1);
        }
    }
#undef LOADKV
}

// ------------------------- fused prep megakernel ---------------------------
constexpr int PREP_BLOCKS = 17408;

__device__ __forceinline__ void tcvt_body(
    float (*t)[33], const float* __restrict__ W, __half* __restrict__ T,
    int K, int N, int bx, int by, int tid)
{
    const int n0 = bx * 32;
    const int k0 = by * 32;
    const int lx = tid & 31;
    const int ly = tid >> 5;
#pragma unroll
    for (int j = 0; j < 4; ++j)
        t[ly + j * 8][lx] = W[(size_t)(k0 + ly + j * 8) * N + n0 + lx];
    __syncthreads();
#pragma unroll
    for (int e = 0; e < 2; ++e) {
        const int idx = tid + e * 256;
        const int row = idx >> 4;
        const int kp  = (idx & 15) * 2;
        const uint32_t hv = pkh(t[kp][row], t[kp + 1][row]);
        *(uint32_t*)&T[(size_t)(n0 + row) * K + k0 + kp] = hv;
    }
}

__global__ void __launch_bounds__(256) prep_all(
    const float* __restrict__ Wq, const float* __restrict__ Wk,
    const float* __restrict__ Wv, const float* __restrict__ Wo,
    const float* __restrict__ W1, const float* __restrict__ W2,
    const float* __restrict__ x, const int* __restrict__ mask,
    __half* __restrict__ wqkvoh, __half* __restrict__ w1h,
    __half* __restrict__ w2h, __half* __restrict__ xh,
    uint16_t* __restrict__ pmh)
{
    __shared__ float t[32][33];
    const int bid = blockIdx.x;
    const int tid = threadIdx.x;

    if (bid < 4096) {
        const int z   = bid >> 10;
        const int rem = bid & 1023;
        const float* W = (z == 0) ? Wq : (z == 1) ? Wk : (z == 2) ? Wv : Wo;
        tcvt_body(t, W, wqkvoh + (size_t)z * D * D, D, D,
                  rem & 31, rem >> 5, tid);
    } else if (bid < 8192) {
        const int rem = bid - 4096;
        tcvt_body(t, W1, w1h, D, DFF, rem & 127, rem >> 7, tid);
    } else if (bid < 12288) {
        const int rem = bid - 8192;
        tcvt_body(t, W2, w2h, DFF, D, rem & 31, rem >> 5, tid);
    } else if (bid < 13312) {
        const int hi = (bid - 12288) * 256 + tid;
        const int4* p = (const int4*)(mask + (size_t)hi * 16);
        uint32_t bits = 0;
#pragma unroll
        for (int j = 0; j < 4; ++j) {
            int4 v = p[j];
            bits |= (uint32_t)(v.x == 1) << (4 * j);
            bits |= (uint32_t)(v.y == 1) << (4 * j + 1);
            bits |= (uint32_t)(v.z == 1) << (4 * j + 2);
            bits |= (uint32_t)(v.w == 1) << (4 * j + 3);
        }
        pmh[hi] = (uint16_t)bits;
    } else {
        const int i = (bid - 13312) * 256 + tid;
        float4 v = ((const float4*)x)[i];
        uint2 hp;
        hp.x = pkh(v.x, v.y); hp.y = pkh(v.z, v.w);
        ((uint2*)xh)[i] = hp;
    }
}

// ---------------- residual + layernorm ------------------------------------
template <int X16, int OUT32>
__global__ void __launch_bounds__(256) ln_res_kernel(
    const float* __restrict__ xres32, const __half* __restrict__ xres16,
    const __half* __restrict__ a,
    const float* __restrict__ g, const float* __restrict__ beta,
    float* __restrict__ out, __half* __restrict__ outh)
{
    const int row = blockIdx.x;
    const int tid = threadIdx.x;
    const uint2 araw = *(const uint2*)&a[(long)row * D + tid * 4];
    const __half2 a01 = *reinterpret_cast<const __half2*>(&araw.x);
    const __half2 a23 = *reinterpret_cast<const __half2*>(&araw.y);
    float4 v;
    v.x = __low2float(a01);  v.y = __high2float(a01);
    v.z = __low2float(a23);  v.w = __high2float(a23);

    float s  = v.x + v.y + v.z + v.w;
    float ss = v.x * v.x + v.y * v.y + v.z * v.z + v.w * v.w;
#pragma unroll
    for (int off = 16; off; off >>= 1) {
        s  += __shfl_xor_sync(0xffffffffu, s,  off);
        ss += __shfl_xor_sync(0xffffffffu, ss, off);
    }
    __shared__ float sbuf[8], ssbuf[8];
    __shared__ float mean_s, rstd_s;
    const int warp = tid >> 5;
    if ((tid & 31) == 0) { sbuf[warp] = s; ssbuf[warp] = ss; }
    __syncthreads();
    if (tid == 0) {
        float t = 0.f, ts = 0.f;
#pragma unroll
        for (int w = 0; w < 8; ++w) { t += sbuf[w]; ts += ssbuf[w]; }
        float mean = t * (1.0f / D);
        float var  = ts * (1.0f / D) - mean * mean;
        mean_s = mean;
        rstd_s = rsqrtf(var + 1e-5f);
    }
    __syncthreads();
    const float mean = mean_s, rstd = rstd_s;

    float4 gv = *(const float4*)&g[tid * 4];
    float4 bv = *(const float4*)&beta[tid * 4];
    float4 xr;
    if (X16) {
        const uint2 xraw = *(const uint2*)&xres16[(long)row * D + tid * 4];
        const __half2 x01 = *reinterpret_cast<const __half2*>(&xraw.x);
        const __half2 x23 = *reinterpret_cast<const __half2*>(&xraw.y);
        xr.x = __low2float(x01);  xr.y = __high2float(x01);
        xr.z = __low2float(x23);  xr.w = __high2float(x23);
    } else {
        xr = *(const float4*)&xres32[(long)row * D + tid * 4];
    }
    float4 ov;
    ov.x = xr.x + (v.x - mean) * rstd * gv.x + bv.x;
    ov.y = xr.y + (v.y - mean) * rstd * gv.y + bv.y;
    ov.z = xr.z + (v.z - mean) * rstd * gv.z + bv.z;
    ov.w = xr.w + (v.w - mean) * rstd * gv.w + bv.w;
    if (OUT32) {
        *(float4*)&out[(long)row * D + tid * 4] = ov;
    } else {
        uint2 hp;
        hp.x = pkh(ov.x, ov.y); hp.y = pkh(ov.z, ov.w);
        *(uint2*)&outh[(long)row * D + tid * 4] = hp;
    }
}

// ---------------------------------------------------------------------------
extern "C" void kernel_launch(void* const* d_in, const int* in_sizes, int n_in,
                              void* d_out, int out_size)
{
    const float* x    = (const float*)d_in[0];
    const int*   mask = (const int*)  d_in[1];
    const float* Wq   = (const float*)d_in[2];
    const float* Wk   = (const float*)d_in[3];
    const float* Wv   = (const float*)d_in[4];
    const float* Wo   = (const float*)d_in[5];
    const float* bo   = (const float*)d_in[6];
    const float* ln1g = (const float*)d_in[7];
    const float* ln1b = (const float*)d_in[8];
    const float* W1   = (const float*)d_in[9];
    const float* b1   = (const float*)d_in[10];
    const float* W2   = (const float*)d_in[11];
    const float* b2   = (const float*)d_in[12];
    const float* ln2g = (const float*)d_in[13];
    const float* ln2b = (const float*)d_in[14];
    float* out = (float*)d_out;

    uint32_t* pm;
    cudaGetSymbolAddress((void**)&pm, g_pm);

    __half *xh, *qkvh, *oh, *t0h, *x1h, *hh, *h2h;
    __half *wqkvoh, *w1h, *w2h;
    cudaGetSymbolAddress((void**)&xh,    g_xh);
    cudaGetSymbolAddress((void**)&qkvh,  g_qkvh);
    cudaGetSymbolAddress((void**)&oh,    g_oh);
    cudaGetSymbolAddress((void**)&t0h,   g_t0h);
    cudaGetSymbolAddress((void**)&x1h,   g_x1h);
    cudaGetSymbolAddress((void**)&hh,    g_hh);
    cudaGetSymbolAddress((void**)&h2h,   g_h2h);
    cudaGetSymbolAddress((void**)&wqkvoh, g_wqkvoh);
    cudaGetSymbolAddress((void**)&w1h,   g_w1h);
    cudaGetSymbolAddress((void**)&w2h,   g_w2h);

    __half* woh = wqkvoh + (size_t)3 * D * D;

    cudaFuncSetAttribute(attn_mma, cudaFuncAttributeMaxDynamicSharedMemorySize, ATTN_SMEM);
    cudaFuncSetAttribute(gemm_mma<0,1>, cudaFuncAttributeMaxDynamicSharedMemorySize, GEMM_SMEM);
    cudaFuncSetAttribute(gemm_mma<1,1>, cudaFuncAttributeMaxDynamicSharedMemorySize, GEMM_SMEM);
    cudaFuncSetAttribute(gemm_mma<2,1>, cudaFuncAttributeMaxDynamicSharedMemorySize, GEMM_SMEM);

    // ALL prep in ONE launch
    prep_all<<<PREP_BLOCKS, 256>>>(Wq, Wk, Wv, Wo, W1, W2, x, mask,
                                   wqkvoh, w1h, w2h, xh, (uint16_t*)pm);

    // fused QKV projection -> fp16; q columns pre-scaled (non-persistent, R13)
    gemm_mma<0,1><<<dim3(QS / 128, M / 128), 256, GEMM_SMEM>>>(
        xh, wqkvoh, nullptr, nullptr, qkvh, QS, D, 1024);

    // flash attention -> oh (balanced 2 tiles per CTA)
    attn_mma<<<AGRID, 256, ATTN_SMEM>>>(qkvh, pm, oh);

    // output projection + bias -> fp16 t0h
    gemm_mma<1,1><<<dim3(D / 128, M / 128), 256, GEMM_SMEM>>>(
        oh, woh, bo, nullptr, t0h, D, D, 0);

    // x1 = x + LN(attn_out) -> fp16 only
    ln_res_kernel<0,0><<<M, 256>>>(x, nullptr, t0h, ln1g, ln1b, nullptr, x1h);

    // FFN (both outputs fp16)
    gemm_mma<2,1><<<dim3(DFF / 128, M / 128), 256, GEMM_SMEM>>>(
        x1h, w1h, b1, nullptr, hh, DFF, D, 0);
    gemm_mma<2,1><<<dim3(D / 128,   M / 128), 256, GEMM_SMEM>>>(
        hh, w2h, b2, nullptr, h2h, D, DFF, 0);

    // out = x1 + LN(h2), fp16 residual -> fp32 out
    ln_res_kernel<1,1><<<M, 256>>>(nullptr, x1h, h2h, ln2g, ln2b, out, nullptr);
}